// round 13
// baseline (speedup 1.0000x reference)
#include <cuda_runtime.h>
#include <cuda_bf16.h>
#include <math.h>
#include <stdint.h>

#define NN    50000
#define NE    800000
#define D_IN  500
#define D_HID 100
#define D_OUT 64

__device__ float g_B1[NN * D_HID];
__device__ float g_B2[NN * D_HID];
__device__ float g_B3[NN * D_HID];
__device__ float g_B4[NN * D_HID];
__device__ float g_dinv[NN];
__device__ int   g_deg[NN];
__device__ int   g_off[NN + 1];
__device__ int   g_cur[NN];
__device__ int   g_el[NE];

// Precomputed weight splits (hi/lo bf16), padded to tile layouts.
__device__ __align__(16) __nv_bfloat16 g_W1h[512 * 112];
__device__ __align__(16) __nv_bfloat16 g_W1l[512 * 112];
__device__ __align__(16) __nv_bfloat16 g_Wh[5][112 * 120];
__device__ __align__(16) __nv_bfloat16 g_Wl[5][112 * 120];

__device__ __forceinline__ unsigned int smem_u32(const void* p) {
    unsigned int a;
    asm("{ .reg .u64 t; cvta.to.shared.u64 t, %1; cvt.u32.u64 %0, t; }"
        : "=r"(a) : "l"(p));
    return a;
}

// ---------------------------------------------------------------------------
// mma.sync helpers
// ---------------------------------------------------------------------------
__device__ __forceinline__ void ldsm4(uint32_t* r, uint32_t addr) {
    asm volatile("ldmatrix.sync.aligned.m8n8.x4.shared.b16 {%0,%1,%2,%3}, [%4];"
                 : "=r"(r[0]), "=r"(r[1]), "=r"(r[2]), "=r"(r[3]) : "r"(addr));
}
__device__ __forceinline__ void ldsm4t(uint32_t* r, uint32_t addr) {
    asm volatile("ldmatrix.sync.aligned.m8n8.x4.trans.shared.b16 {%0,%1,%2,%3}, [%4];"
                 : "=r"(r[0]), "=r"(r[1]), "=r"(r[2]), "=r"(r[3]) : "r"(addr));
}
__device__ __forceinline__ void mma16816(float* c, const uint32_t* a,
                                         uint32_t b0, uint32_t b1) {
    asm volatile(
        "mma.sync.aligned.m16n8k16.row.col.f32.bf16.bf16.f32 "
        "{%0,%1,%2,%3}, {%4,%5,%6,%7}, {%8,%9}, {%0,%1,%2,%3};"
        : "+f"(c[0]), "+f"(c[1]), "+f"(c[2]), "+f"(c[3])
        : "r"(a[0]), "r"(a[1]), "r"(a[2]), "r"(a[3]), "r"(b0), "r"(b1));
}
__device__ __forceinline__ uint32_t bfpack(float a, float b) {
    __nv_bfloat162 t = __floats2bfloat162_rn(a, b);
    return *(uint32_t*)&t;
}
__device__ __forceinline__ void split4(float4 v, uint2& hi, uint2& lo) {
    __nv_bfloat16 a = __float2bfloat16(v.x), b = __float2bfloat16(v.y);
    __nv_bfloat16 c = __float2bfloat16(v.z), d = __float2bfloat16(v.w);
    float fa = __bfloat162float(a), fb = __bfloat162float(b);
    float fc = __bfloat162float(c), fd = __bfloat162float(d);
    hi.x = bfpack(fa, fb);
    hi.y = bfpack(fc, fd);
    lo.x = bfpack(v.x - fa, v.y - fb);
    lo.y = bfpack(v.z - fc, v.w - fd);
}

// ---------------------------------------------------------------------------
// Weight split precompute (once, ~3us)
// ---------------------------------------------------------------------------
__global__ void wsplit_kernel(const float* __restrict__ W1,
                              const float* __restrict__ W2,
                              const float* __restrict__ Ws,
                              const float* __restrict__ Wr,
                              const float* __restrict__ c1,
                              const float* __restrict__ c2)
{
    int i = blockIdx.x * blockDim.x + threadIdx.x;
    if (i < 512 * 112) {
        int k = i / 112, c = i % 112;
        float v = (k < D_IN && c < D_HID) ? W1[k * D_HID + c] : 0.f;
        __nv_bfloat16 h = __float2bfloat16(v);
        g_W1h[i] = h;
        g_W1l[i] = __float2bfloat16(v - __bfloat162float(h));
    } else {
        int j = i - 512 * 112;
        if (j < 5 * 13440) {
            int m = j / 13440, r = j % 13440;
            int k = r / 120, n = r % 120;
            const float* Wp; int NO;
            switch (m) {
                case 0: Wp = W2; NO = 100; break;
                case 1: Wp = Ws; NO = 100; break;
                case 2: Wp = Wr; NO = 100; break;
                case 3: Wp = c1; NO = 100; break;
                default: Wp = c2; NO = 64; break;
            }
            float v = (k < 100 && n < NO) ? Wp[k * NO + n] : 0.f;
            __nv_bfloat16 h = __float2bfloat16(v);
            g_Wh[m][r] = h;
            g_Wl[m][r] = __float2bfloat16(v - __bfloat162float(h));
        }
    }
}

// ---------------------------------------------------------------------------
// CSR construction (unchanged)
// ---------------------------------------------------------------------------
__global__ void deg_zero_kernel() {
    int i = blockIdx.x * blockDim.x + threadIdx.x;
    if (i < NN / 4) ((int4*)g_deg)[i] = make_int4(0, 0, 0, 0);
}
__global__ void deg_count_kernel(const int* __restrict__ tgt) {
    int base = (blockIdx.x * blockDim.x + threadIdx.x) * 4;
    if (base + 3 < NE) {
        int4 t = *(const int4*)(tgt + base);
        atomicAdd(&g_deg[t.x], 1);
        atomicAdd(&g_deg[t.y], 1);
        atomicAdd(&g_deg[t.z], 1);
        atomicAdd(&g_deg[t.w], 1);
    }
}
__global__ void scan_kernel() {
    __shared__ int warp_sums[32];
    const int tid = threadIdx.x;
    const int lane = tid & 31, wid = tid >> 5;
    int carry = 0;
    for (int base = 0; base < NN; base += 1024) {
        int i = base + tid;
        int v = (i < NN) ? g_deg[i] : 0;
        int x = v;
#pragma unroll
        for (int d = 1; d < 32; d <<= 1) {
            int t = __shfl_up_sync(0xffffffffu, x, d);
            if (lane >= d) x += t;
        }
        if (lane == 31) warp_sums[wid] = x;
        __syncthreads();
        if (wid == 0) {
            int s = warp_sums[lane];
#pragma unroll
            for (int d = 1; d < 32; d <<= 1) {
                int t = __shfl_up_sync(0xffffffffu, s, d);
                if (lane >= d) s += t;
            }
            warp_sums[lane] = s;
        }
        __syncthreads();
        int warp_prefix = (wid > 0) ? warp_sums[wid - 1] : 0;
        int incl = warp_prefix + x;
        if (i < NN) {
            g_off[i]  = carry + incl - v;
            g_dinv[i] = rsqrtf((float)(v + 1));
            g_cur[i]  = 0;
        }
        carry += warp_sums[31];
        __syncthreads();
    }
    if (tid == 0) g_off[NN] = carry;
}
__global__ void fill_kernel(const int* __restrict__ src, const int* __restrict__ tgt) {
    int base = (blockIdx.x * blockDim.x + threadIdx.x) * 4;
    if (base + 3 < NE) {
        int4 t = *(const int4*)(tgt + base);
        int4 s = *(const int4*)(src + base);
        int p0 = g_off[t.x] + atomicAdd(&g_cur[t.x], 1);
        int p1 = g_off[t.y] + atomicAdd(&g_cur[t.y], 1);
        int p2 = g_off[t.z] + atomicAdd(&g_cur[t.z], 1);
        int p3 = g_off[t.w] + atomicAdd(&g_cur[t.w], 1);
        g_el[p0] = s.x; g_el[p1] = s.y; g_el[p2] = s.z; g_el[p3] = s.w;
    }
}

// ---------------------------------------------------------------------------
// Big GEMM via mma.sync bf16 split (unchanged R12 winner)
// ---------------------------------------------------------------------------
#define MB_AHI 0
#define MB_ALO 6144
#define MB_BHI 12288
#define MB_BLO 16128
#define MB_SMEM 51200

__global__ void __launch_bounds__(256)
gemm_big_mma(const float* __restrict__ X,
             const float* __restrict__ bias,
             const float* __restrict__ gamma,
             const float* __restrict__ beta,
             float* __restrict__ out)
{
    extern __shared__ char smx[];
    const uint32_t sb = smem_u32(smx);
    const int tid = threadIdx.x;
    const int wid = tid >> 5, lane = tid & 31;
    const int r0 = blockIdx.x * 128;
    const int m0 = wid * 16;

    float acc[56];
#pragma unroll
    for (int i = 0; i < 56; i++) acc[i] = 0.f;

    float4 ax0, ax1;
    uint4 w0r, w1r;
    const int ar = tid >> 1, akc = (tid & 1) * 8;
    const int s0buf = tid / 224, s0idx = tid % 224;
    const int s0row = s0idx / 14, s0c = s0idx % 14;
    const int s1idx = tid + 32;
    const int s1row = s1idx / 14, s1c = s1idx % 14;

    auto load_chunk = [&](int t) {
        const int k0 = t * 16;
        int row = r0 + ar;
        const float* xp = X + (size_t)row * D_IN + k0 + akc;
        if (row < NN && k0 + akc + 8 <= D_IN) {
            ax0 = *(const float4*)xp;
            ax1 = *(const float4*)(xp + 4);
        } else {
            float tv[8];
#pragma unroll
            for (int j = 0; j < 8; j++)
                tv[j] = (row < NN && k0 + akc + j < D_IN) ? xp[j] : 0.f;
            ax0 = make_float4(tv[0], tv[1], tv[2], tv[3]);
            ax1 = make_float4(tv[4], tv[5], tv[6], tv[7]);
        }
        {
            const __nv_bfloat16* srcw = s0buf ? g_W1l : g_W1h;
            w0r = *(const uint4*)(srcw + (k0 + s0row) * 112 + s0c * 8);
        }
        if (tid < 192)
            w1r = *(const uint4*)(g_W1l + (k0 + s1row) * 112 + s1c * 8);
    };

    auto sts_chunk = [&]() {
        uint2 h0, l0, h1, l1;
        split4(ax0, h0, l0);
        split4(ax1, h1, l1);
        uint32_t aoff = (uint32_t)(ar * 48 + akc * 2);
        *(uint4*)(smx + MB_AHI + aoff) = make_uint4(h0.x, h0.y, h1.x, h1.y);
        *(uint4*)(smx + MB_ALO + aoff) = make_uint4(l0.x, l0.y, l1.x, l1.y);
        *(uint4*)(smx + (s0buf ? MB_BLO : MB_BHI) + s0row * 240 + s0c * 16) = w0r;
        if (tid < 192)
            *(uint4*)(smx + MB_BLO + s1row * 240 + s1c * 16) = w1r;
    };

    const uint32_t a_addr_off =
        (uint32_t)((m0 + (lane & 15)) * 48 + (lane >> 4) * 16);
    const uint32_t b_addr_row = (uint32_t)((lane & 15) * 240 + (lane >> 4) * 16);

    load_chunk(0);
    for (int t = 0; t < 32; t++) {
        __syncthreads();
        sts_chunk();
        __syncthreads();
        if (t + 1 < 32) load_chunk(t + 1);

        uint32_t ah[4], al[4];
        ldsm4(ah, sb + MB_AHI + a_addr_off);
        ldsm4(al, sb + MB_ALO + a_addr_off);
#pragma unroll
        for (int p = 0; p < 7; p++) {
            uint32_t bh[4], bl[4];
            uint32_t bo = b_addr_row + (uint32_t)(p * 32);
            ldsm4t(bh, sb + MB_BHI + bo);
            ldsm4t(bl, sb + MB_BLO + bo);
#pragma unroll
            for (int h = 0; h < 2; h++) {
                float* c = &acc[p * 8 + h * 4];
                mma16816(c, ah, bh[2 * h], bh[2 * h + 1]);
                mma16816(c, ah, bl[2 * h], bl[2 * h + 1]);
                mma16816(c, al, bh[2 * h], bh[2 * h + 1]);
            }
        }
    }

    __syncthreads();
    float* sC = (float*)smx;
#pragma unroll
    for (int p = 0; p < 7; p++) {
#pragma unroll
        for (int h = 0; h < 2; h++) {
            int n0 = p * 16 + h * 8;
            int col = n0 + (lane & 3) * 2;
            if (col < D_HID) {
                int rA = m0 + (lane >> 2);
                float b0v = bias[col], b1v = bias[col + 1];
                const float* c = &acc[p * 8 + h * 4];
                sC[rA * D_HID + col]           = c[0] + b0v;
                sC[rA * D_HID + col + 1]       = c[1] + b1v;
                sC[(rA + 8) * D_HID + col]     = c[2] + b0v;
                sC[(rA + 8) * D_HID + col + 1] = c[3] + b1v;
            }
        }
    }
    __syncthreads();
    for (int r = wid; r < 128; r += 8) {
        int row = r0 + r;
        float vals[4];
        float s = 0.f, sq = 0.f;
#pragma unroll
        for (int q = 0; q < 4; q++) {
            int c = lane + 32 * q;
            float v = (c < D_HID) ? sC[r * D_HID + c] : 0.f;
            vals[q] = v; s += v; sq += v * v;
        }
#pragma unroll
        for (int o2 = 16; o2 > 0; o2 >>= 1) {
            s  += __shfl_xor_sync(0xffffffffu, s,  o2);
            sq += __shfl_xor_sync(0xffffffffu, sq, o2);
        }
        float mean = s / D_HID;
        float var  = sq / D_HID - mean * mean;
        float rstd = rsqrtf(var + 1e-5f);
        if (row < NN) {
#pragma unroll
            for (int q = 0; q < 4; q++) {
                int c = lane + 32 * q;
                if (c < D_HID)
                    out[row * D_HID + c] =
                        fmaxf((vals[q] - mean) * rstd * gamma[c] + beta[c], 0.f);
            }
        }
    }
}

// ---------------------------------------------------------------------------
// Small GEMM on mma.sync split-bf16, 512 threads (16 warps).
// Warp = (row-strip = wid>>1, n-half = wid&1); each warp owns 3-4 n-tiles.
// A: [128][120 bf16] hi/lo (pitch 240B). Single B buffer (dual: 2 passes).
// NOUT = 100 or 64. EPI: 2 = +bias,LN,ReLU | 3 = *dinv | 4 = dual (wA+bias, wB)
// ---------------------------------------------------------------------------
#define SG_AHI 0
#define SG_ALO 30720
#define SG_BHI 61440
#define SG_BLO 88320
#define SG_TOT 115200

template<int NOUT, int EPI>
__global__ void __launch_bounds__(512)
gemm_small_mma(const float* __restrict__ A, int widx, int widx2,
               const float* __restrict__ bias,
               const float* __restrict__ gamma,
               const float* __restrict__ beta,
               float* __restrict__ out,
               float* __restrict__ out2)
{
    constexpr int NP  = (NOUT == 64) ? 4 : 7;       // n16-tiles total
    constexpr int MID = (NP + 1) / 2;               // tiles in half 0
    extern __shared__ char smx[];
    const uint32_t sb = smem_u32(smx);
    const int tid = threadIdx.x;
    const int wid = tid >> 5, lane = tid & 31;
    const int r0 = blockIdx.x * 128;
    const int m0 = (wid >> 1) * 16;                 // row strip
    const int nh = wid & 1;                         // n-half
    const int p_start = nh ? MID : 0;
    const int p_end   = nh ? NP  : MID;

    // Zero A region (covers k-pad cols 100..119)
    for (int i = tid * 16; i < 61440; i += 512 * 16)
        *(uint4*)(smx + i) = make_uint4(0, 0, 0, 0);
    __syncthreads();

    // Convert A [128 x 100] -> hi/lo bf16, pitch 240B
    for (int i = tid; i < 128 * 25; i += 512) {
        int r = i / 25, q = i % 25;
        int row = r0 + r;
        float4 v = make_float4(0.f, 0.f, 0.f, 0.f);
        if (row < NN) v = *(const float4*)(A + (size_t)row * 100 + q * 4);
        uint2 hi, lo; split4(v, hi, lo);
        *(uint2*)(smx + SG_AHI + r * 240 + q * 8) = hi;
        *(uint2*)(smx + SG_ALO + r * 240 + q * 8) = lo;
    }
    // Copy B tile (precomputed, layout-identical, padding included)
    {
        const uint4* gh = (const uint4*)g_Wh[widx];
        const uint4* gl = (const uint4*)g_Wl[widx];
        for (int i = tid; i < 1680; i += 512) {
            ((uint4*)(smx + SG_BHI))[i] = gh[i];
            ((uint4*)(smx + SG_BLO))[i] = gl[i];
        }
    }
    __syncthreads();

    const uint32_t a_off = (uint32_t)((m0 + (lane & 15)) * 240 + (lane >> 4) * 16);
    const uint32_t b_row = (uint32_t)((lane & 15) * 240 + (lane >> 4) * 16);

    float acc[MID * 8];
    auto run_pass = [&]() {
#pragma unroll
        for (int i = 0; i < MID * 8; i++) acc[i] = 0.f;
#pragma unroll
        for (int kc = 0; kc < 7; kc++) {
            uint32_t ah[4], al[4];
            ldsm4(ah, sb + SG_AHI + a_off + kc * 32);
            ldsm4(al, sb + SG_ALO + a_off + kc * 32);
            for (int p = p_start; p < p_end; p++) {
                uint32_t bh[4], bl[4];
                uint32_t bo = b_row + (uint32_t)(kc * 3840 + p * 32);
                ldsm4t(bh, sb + SG_BHI + bo);
                ldsm4t(bl, sb + SG_BLO + bo);
#pragma unroll
                for (int h = 0; h < 2; h++) {
                    float* c = &acc[(p - p_start) * 8 + h * 4];
                    mma16816(c, ah, bh[2 * h], bh[2 * h + 1]);
                    mma16816(c, ah, bl[2 * h], bl[2 * h + 1]);
                    mma16816(c, al, bh[2 * h], bh[2 * h + 1]);
                }
            }
        }
    };

    run_pass();

    const int rA = m0 + (lane >> 2);
    const int rowA = r0 + rA, rowB = rowA + 8;

    if (EPI == 2) {
        __syncthreads();
        float* sC = (float*)smx;
        for (int p = p_start; p < p_end; p++) {
#pragma unroll
            for (int h = 0; h < 2; h++) {
                int col = p * 16 + h * 8 + (lane & 3) * 2;
                if (col < NOUT) {
                    float b0v = bias[col], b1v = bias[col + 1];
                    const float* c = &acc[(p - p_start) * 8 + h * 4];
                    sC[rA * NOUT + col]           = c[0] + b0v;
                    sC[rA * NOUT + col + 1]       = c[1] + b1v;
                    sC[(rA + 8) * NOUT + col]     = c[2] + b0v;
                    sC[(rA + 8) * NOUT + col + 1] = c[3] + b1v;
                }
            }
        }
        __syncthreads();
        for (int r = wid; r < 128; r += 16) {
            int row = r0 + r;
            float vals[4];
            float s = 0.f, sq = 0.f;
#pragma unroll
            for (int q = 0; q < 4; q++) {
                int c = lane + 32 * q;
                float v = (c < NOUT) ? sC[r * NOUT + c] : 0.f;
                vals[q] = v; s += v; sq += v * v;
            }
#pragma unroll
            for (int o2 = 16; o2 > 0; o2 >>= 1) {
                s  += __shfl_xor_sync(0xffffffffu, s,  o2);
                sq += __shfl_xor_sync(0xffffffffu, sq, o2);
            }
            float mean = s / NOUT;
            float var  = sq / NOUT - mean * mean;
            float rstd = rsqrtf(var + 1e-5f);
            if (row < NN) {
#pragma unroll
                for (int q = 0; q < 4; q++) {
                    int c = lane + 32 * q;
                    if (c < NOUT)
                        out[row * NOUT + c] =
                            fmaxf((vals[q] - mean) * rstd * gamma[c] + beta[c], 0.f);
                }
            }
        }
    } else if (EPI == 3) {
        float d0 = (rowA < NN) ? g_dinv[rowA] : 0.f;
        float d1 = (rowB < NN) ? g_dinv[rowB] : 0.f;
        for (int p = p_start; p < p_end; p++) {
#pragma unroll
            for (int h = 0; h < 2; h++) {
                int col = p * 16 + h * 8 + (lane & 3) * 2;
                if (col < NOUT) {
                    const float* c = &acc[(p - p_start) * 8 + h * 4];
                    if (rowA < NN) {
                        out[(size_t)rowA * NOUT + col]     = d0 * c[0];
                        out[(size_t)rowA * NOUT + col + 1] = d0 * c[1];
                    }
                    if (rowB < NN) {
                        out[(size_t)rowB * NOUT + col]     = d1 * c[2];
                        out[(size_t)rowB * NOUT + col + 1] = d1 * c[3];
                    }
                }
            }
        }
    } else {  // EPI == 4: dual, two passes over same B buffer
        for (int p = p_start; p < p_end; p++) {
#pragma unroll
            for (int h = 0; h < 2; h++) {
                int col = p * 16 + h * 8 + (lane & 3) * 2;
                if (col < NOUT) {
                    const float* c = &acc[(p - p_start) * 8 + h * 4];
                    float b0v = bias[col], b1v = bias[col + 1];
                    if (rowA < NN) {
                        out[(size_t)rowA * NOUT + col]     = c[0] + b0v;
                        out[(size_t)rowA * NOUT + col + 1] = c[1] + b1v;
                    }
                    if (rowB < NN) {
                        out[(size_t)rowB * NOUT + col]     = c[2] + b0v;
                        out[(size_t)rowB * NOUT + col + 1] = c[3] + b1v;
                    }
                }
            }
        }
        __syncthreads();
        {
            const uint4* gh = (const uint4*)g_Wh[widx2];
            const uint4* gl = (const uint4*)g_Wl[widx2];
            for (int i = tid; i < 1680; i += 512) {
                ((uint4*)(smx + SG_BHI))[i] = gh[i];
                ((uint4*)(smx + SG_BLO))[i] = gl[i];
            }
        }
        __syncthreads();
        run_pass();
        for (int p = p_start; p < p_end; p++) {
#pragma unroll
            for (int h = 0; h < 2; h++) {
                int col = p * 16 + h * 8 + (lane & 3) * 2;
                if (col < NOUT) {
                    const float* c = &acc[(p - p_start) * 8 + h * 4];
                    if (rowA < NN) {
                        out2[(size_t)rowA * NOUT + col]     = c[0];
                        out2[(size_t)rowA * NOUT + col + 1] = c[1];
                    }
                    if (rowB < NN) {
                        out2[(size_t)rowB * NOUT + col]     = c[2];
                        out2[(size_t)rowB * NOUT + col + 1] = c[3];
                    }
                }
            }
        }
    }
}

// ---------------------------------------------------------------------------
// Gather aggregation (warp per node), 4-way edge ILP. (unchanged)
// ---------------------------------------------------------------------------
template<int M4, int MODE>
__global__ void gather_kernel(const float* __restrict__ h,
                              const float* __restrict__ self,
                              const float* __restrict__ bias,
                              float* __restrict__ out)
{
    int w = (blockIdx.x * blockDim.x + threadIdx.x) >> 5;
    if (w >= NN) return;
    const int lane = threadIdx.x & 31;
    const bool act = lane < M4;
    const float4* h4 = (const float4*)h;

    float4 a0 = make_float4(0.f, 0.f, 0.f, 0.f);
    float4 a1 = a0, a2 = a0, a3 = a0;
    if (act) {
        if (MODE == 0) a0 = ((const float4*)self)[w * M4 + lane];
        else           a0 = h4[w * M4 + lane];
    }

    const int off = g_off[w];
    const int dg  = g_off[w + 1] - off;
    for (int base = 0; base < dg; base += 32) {
        int idx = base + lane;
        int myel = (idx < dg) ? g_el[off + idx] : 0;
        int cnt = dg - base; if (cnt > 32) cnt = 32;
        int j = 0;
        for (; j + 3 < cnt; j += 4) {
            int s0 = __shfl_sync(0xffffffffu, myel, j);
            int s1 = __shfl_sync(0xffffffffu, myel, j + 1);
            int s2 = __shfl_sync(0xffffffffu, myel, j + 2);
            int s3 = __shfl_sync(0xffffffffu, myel, j + 3);
            if (act) {
                float4 v0 = h4[s0 * M4 + lane];
                float4 v1 = h4[s1 * M4 + lane];
                float4 v2 = h4[s2 * M4 + lane];
                float4 v3 = h4[s3 * M4 + lane];
                a0.x += v0.x; a0.y += v0.y; a0.z += v0.z; a0.w += v0.w;
                a1.x += v1.x; a1.y += v1.y; a1.z += v1.z; a1.w += v1.w;
                a2.x += v2.x; a2.y += v2.y; a2.z += v2.z; a2.w += v2.w;
                a3.x += v3.x; a3.y += v3.y; a3.z += v3.z; a3.w += v3.w;
            }
        }
        for (; j < cnt; j++) {
            int s0 = __shfl_sync(0xffffffffu, myel, j);
            if (act) {
                float4 v0 = h4[s0 * M4 + lane];
                a0.x += v0.x; a0.y += v0.y; a0.z += v0.z; a0.w += v0.w;
            }
        }
    }
    float4 acc;
    acc.x = (a0.x + a1.x) + (a2.x + a3.x);
    acc.y = (a0.y + a1.y) + (a2.y + a3.y);
    acc.z = (a0.z + a1.z) + (a2.z + a3.z);
    acc.w = (a0.w + a1.w) + (a2.w + a3.w);

    if (MODE == 0) {
        if (act) {
            float4 o;
            o.x = fmaxf(acc.x, 0.f); o.y = fmaxf(acc.y, 0.f);
            o.z = fmaxf(acc.z, 0.f); o.w = fmaxf(acc.w, 0.f);
            ((float4*)out)[w * M4 + lane] = o;
        }
    } else if (MODE == 1) {
        if (act) {
            float di = g_dinv[w];
            float4 b = ((const float4*)bias)[lane];
            float4 o;
            o.x = fmaxf(fmaf(di, acc.x, b.x), 0.f);
            o.y = fmaxf(fmaf(di, acc.y, b.y), 0.f);
            o.z = fmaxf(fmaf(di, acc.z, b.z), 0.f);
            o.w = fmaxf(fmaf(di, acc.w, b.w), 0.f);
            ((float4*)out)[w * M4 + lane] = o;
        }
    } else {
        float di = g_dinv[w];
        float4 v = make_float4(0.f, 0.f, 0.f, 0.f);
        if (act) {
            float4 b = ((const float4*)bias)[lane];
            v.x = fmaf(di, acc.x, b.x); v.y = fmaf(di, acc.y, b.y);
            v.z = fmaf(di, acc.z, b.z); v.w = fmaf(di, acc.w, b.w);
        }
        float m = act ? fmaxf(fmaxf(v.x, v.y), fmaxf(v.z, v.w)) : -3.4e38f;
#pragma unroll
        for (int o2 = 16; o2 > 0; o2 >>= 1)
            m = fmaxf(m, __shfl_xor_sync(0xffffffffu, m, o2));
        float se = act ? (expf(v.x - m) + expf(v.y - m) + expf(v.z - m) + expf(v.w - m)) : 0.f;
#pragma unroll
        for (int o2 = 16; o2 > 0; o2 >>= 1)
            se += __shfl_xor_sync(0xffffffffu, se, o2);
        float lse = m + logf(se);
        if (act) {
            float4 o;
            o.x = v.x - lse; o.y = v.y - lse; o.z = v.z - lse; o.w = v.w - lse;
            ((float4*)out)[w * M4 + lane] = o;
        }
    }
}

extern "C" void kernel_launch(void* const* d_in, const int* in_sizes, int n_in,
                              void* d_out, int out_size)
{
    const float* X     = (const float*)d_in[0];
    const int*   ei    = (const int*)  d_in[1];
    const float* W1    = (const float*)d_in[3];
    const float* b1    = (const float*)d_in[4];
    const float* g1    = (const float*)d_in[5];
    const float* be1   = (const float*)d_in[6];
    const float* W2    = (const float*)d_in[7];
    const float* b2    = (const float*)d_in[8];
    const float* g2    = (const float*)d_in[9];
    const float* be2   = (const float*)d_in[10];
    const float* Wrel  = (const float*)d_in[11];
    const float* Wself = (const float*)d_in[12];
    const float* rb    = (const float*)d_in[13];
    const float* c1W   = (const float*)d_in[14];
    const float* c1b   = (const float*)d_in[15];
    const float* c2W   = (const float*)d_in[16];
    const float* c2b   = (const float*)d_in[17];
    float* out = (float*)d_out;

    const int* src = ei;
    const int* tgt = ei + NE;

    float *B1, *B2, *B3, *B4;
    cudaGetSymbolAddress((void**)&B1, g_B1);
    cudaGetSymbolAddress((void**)&B2, g_B2);
    cudaGetSymbolAddress((void**)&B3, g_B3);
    cudaGetSymbolAddress((void**)&B4, g_B4);

    cudaFuncSetAttribute(gemm_big_mma,
                         cudaFuncAttributeMaxDynamicSharedMemorySize, MB_SMEM);
    cudaFuncSetAttribute(gemm_small_mma<100, 2>,
                         cudaFuncAttributeMaxDynamicSharedMemorySize, SG_TOT);
    cudaFuncSetAttribute(gemm_small_mma<100, 3>,
                         cudaFuncAttributeMaxDynamicSharedMemorySize, SG_TOT);
    cudaFuncSetAttribute(gemm_small_mma<100, 4>,
                         cudaFuncAttributeMaxDynamicSharedMemorySize, SG_TOT);
    cudaFuncSetAttribute(gemm_small_mma<64, 3>,
                         cudaFuncAttributeMaxDynamicSharedMemorySize, SG_TOT);

    const int GB = (NN + 127) / 128;   // 391
    const int GGATHER = (NN * 32 + 255) / 256;

    // Fork a side stream for the CSR build (overlaps the transform GEMMs).
    cudaStream_t s2;
    cudaEvent_t evFork, evJoin;
    cudaStreamCreateWithFlags(&s2, cudaStreamNonBlocking);
    cudaEventCreateWithFlags(&evFork, cudaEventDisableTiming);
    cudaEventCreateWithFlags(&evJoin, cudaEventDisableTiming);

    cudaEventRecord(evFork, 0);
    cudaStreamWaitEvent(s2, evFork, 0);

    deg_zero_kernel <<<(NN / 4 + 255) / 256, 256, 0, s2>>>();
    deg_count_kernel<<<(NE / 4 + 255) / 256, 256, 0, s2>>>(tgt);
    scan_kernel     <<<1, 1024, 0, s2>>>();
    fill_kernel     <<<(NE / 4 + 255) / 256, 256, 0, s2>>>(src, tgt);
    cudaEventRecord(evJoin, s2);

    // Weight splits (once, tiny)
    wsplit_kernel<<<(512 * 112 + 5 * 13440 + 255) / 256, 256>>>(
        W1, W2, Wself, Wrel, c1W, c2W);

    // transform: (Linear -> LN -> ReLU) x2, both on mma.sync tensor path
    gemm_big_mma<<<GB, 256, MB_SMEM>>>(X, b1, g1, be1, B1);
    gemm_small_mma<100, 2><<<GB, 512, SG_TOT>>>(
        B1, 0, 0, b2, g2, be2, B2, nullptr);

    // RGCN: dual GEMM (Wself + rb -> B3, Wrel -> B4), then gather
    gemm_small_mma<100, 4><<<GB, 512, SG_TOT>>>(
        B2, 1, 2, rb, nullptr, nullptr, B3, B4);

    cudaStreamWaitEvent(0, evJoin, 0);
    gather_kernel<25, 0><<<GGATHER, 256>>>(B4, B3, nullptr, B1);

    // GCNConv1
    gemm_small_mma<100, 3><<<GB, 512, SG_TOT>>>(
        B1, 3, 0, nullptr, nullptr, nullptr, B2, nullptr);
    gather_kernel<25, 1><<<GGATHER, 256>>>(B2, nullptr, c1b, B3);

    // GCNConv2 (->64) + log_softmax
    gemm_small_mma<64, 3><<<GB, 512, SG_TOT>>>(
        B3, 4, 0, nullptr, nullptr, nullptr, B4, nullptr);
    gather_kernel<16, 2><<<GGATHER, 256>>>(B4, nullptr, c2b, out);

    cudaEventDestroy(evFork);
    cudaEventDestroy(evJoin);
    cudaStreamDestroy(s2);
}

// round 15
// speedup vs baseline: 1.2313x; 1.2313x over previous
#include <cuda_runtime.h>
#include <cuda_bf16.h>
#include <math.h>
#include <stdint.h>

#define NN    50000
#define NE    800000
#define D_IN  500
#define D_HID 100
#define D_OUT 64

__device__ float g_B1[NN * D_HID];
__device__ float g_B2[NN * D_HID];
__device__ float g_B3[NN * D_HID];
__device__ float g_B4[NN * D_HID];
__device__ float g_dinv[NN];
__device__ int   g_deg[NN];
__device__ int   g_off[NN + 1];
__device__ int   g_cur[NN];
__device__ int   g_el[NE];

// Precomputed weight splits (hi/lo bf16), padded to tile layouts.
// W1: [512][112]  (k-major, zero-padded)
// small weights [5]: [112][120] (pitch 240B) 0=W2 1=Wself 2=Wrel 3=c1W 4=c2W
__device__ __align__(16) __nv_bfloat16 g_W1h[512 * 112];
__device__ __align__(16) __nv_bfloat16 g_W1l[512 * 112];
__device__ __align__(16) __nv_bfloat16 g_Wh[5][112 * 120];
__device__ __align__(16) __nv_bfloat16 g_Wl[5][112 * 120];

__device__ __forceinline__ unsigned int smem_u32(const void* p) {
    unsigned int a;
    asm("{ .reg .u64 t; cvta.to.shared.u64 t, %1; cvt.u32.u64 %0, t; }"
        : "=r"(a) : "l"(p));
    return a;
}

// ---------------------------------------------------------------------------
// mma.sync helpers (base-ISA tensor path; compiles for plain compute_103)
// ---------------------------------------------------------------------------
__device__ __forceinline__ void ldsm4(uint32_t* r, uint32_t addr) {
    asm volatile("ldmatrix.sync.aligned.m8n8.x4.shared.b16 {%0,%1,%2,%3}, [%4];"
                 : "=r"(r[0]), "=r"(r[1]), "=r"(r[2]), "=r"(r[3]) : "r"(addr));
}
__device__ __forceinline__ void ldsm4t(uint32_t* r, uint32_t addr) {
    asm volatile("ldmatrix.sync.aligned.m8n8.x4.trans.shared.b16 {%0,%1,%2,%3}, [%4];"
                 : "=r"(r[0]), "=r"(r[1]), "=r"(r[2]), "=r"(r[3]) : "r"(addr));
}
__device__ __forceinline__ void mma16816(float* c, const uint32_t* a,
                                         uint32_t b0, uint32_t b1) {
    asm volatile(
        "mma.sync.aligned.m16n8k16.row.col.f32.bf16.bf16.f32 "
        "{%0,%1,%2,%3}, {%4,%5,%6,%7}, {%8,%9}, {%0,%1,%2,%3};"
        : "+f"(c[0]), "+f"(c[1]), "+f"(c[2]), "+f"(c[3])
        : "r"(a[0]), "r"(a[1]), "r"(a[2]), "r"(a[3]), "r"(b0), "r"(b1));
}
__device__ __forceinline__ uint32_t bfpack(float a, float b) {
    __nv_bfloat162 t = __floats2bfloat162_rn(a, b);
    return *(uint32_t*)&t;
}
__device__ __forceinline__ void split4(float4 v, uint2& hi, uint2& lo) {
    __nv_bfloat16 a = __float2bfloat16(v.x), b = __float2bfloat16(v.y);
    __nv_bfloat16 c = __float2bfloat16(v.z), d = __float2bfloat16(v.w);
    float fa = __bfloat162float(a), fb = __bfloat162float(b);
    float fc = __bfloat162float(c), fd = __bfloat162float(d);
    hi.x = bfpack(fa, fb);
    hi.y = bfpack(fc, fd);
    lo.x = bfpack(v.x - fa, v.y - fb);
    lo.y = bfpack(v.z - fc, v.w - fd);
}

// ---------------------------------------------------------------------------
// Weight split precompute (runs once per launch, ~3us)
// ---------------------------------------------------------------------------
__global__ void wsplit_kernel(const float* __restrict__ W1,
                              const float* __restrict__ W2,
                              const float* __restrict__ Ws,
                              const float* __restrict__ Wr,
                              const float* __restrict__ c1,
                              const float* __restrict__ c2)
{
    int i = blockIdx.x * blockDim.x + threadIdx.x;
    if (i < 512 * 112) {
        int k = i / 112, c = i % 112;
        float v = (k < D_IN && c < D_HID) ? W1[k * D_HID + c] : 0.f;
        __nv_bfloat16 h = __float2bfloat16(v);
        g_W1h[i] = h;
        g_W1l[i] = __float2bfloat16(v - __bfloat162float(h));
    } else {
        int j = i - 512 * 112;
        if (j < 5 * 13440) {
            int m = j / 13440, r = j % 13440;
            int k = r / 120, n = r % 120;
            const float* Wp; int NO;
            switch (m) {
                case 0: Wp = W2; NO = 100; break;
                case 1: Wp = Ws; NO = 100; break;
                case 2: Wp = Wr; NO = 100; break;
                case 3: Wp = c1; NO = 100; break;
                default: Wp = c2; NO = 64; break;
            }
            float v = (k < 100 && n < NO) ? Wp[k * NO + n] : 0.f;
            __nv_bfloat16 h = __float2bfloat16(v);
            g_Wh[m][r] = h;
            g_Wl[m][r] = __float2bfloat16(v - __bfloat162float(h));
        }
    }
}

// ---------------------------------------------------------------------------
// CSR construction
// ---------------------------------------------------------------------------
__global__ void deg_zero_kernel() {
    int i = blockIdx.x * blockDim.x + threadIdx.x;
    if (i < NN / 4) ((int4*)g_deg)[i] = make_int4(0, 0, 0, 0);
}
__global__ void deg_count_kernel(const int* __restrict__ tgt) {
    int base = (blockIdx.x * blockDim.x + threadIdx.x) * 4;
    if (base + 3 < NE) {
        int4 t = *(const int4*)(tgt + base);
        atomicAdd(&g_deg[t.x], 1);
        atomicAdd(&g_deg[t.y], 1);
        atomicAdd(&g_deg[t.z], 1);
        atomicAdd(&g_deg[t.w], 1);
    }
}
__global__ void scan_kernel() {
    __shared__ int warp_sums[32];
    const int tid = threadIdx.x;
    const int lane = tid & 31, wid = tid >> 5;
    int carry = 0;
    for (int base = 0; base < NN; base += 1024) {
        int i = base + tid;
        int v = (i < NN) ? g_deg[i] : 0;
        int x = v;
#pragma unroll
        for (int d = 1; d < 32; d <<= 1) {
            int t = __shfl_up_sync(0xffffffffu, x, d);
            if (lane >= d) x += t;
        }
        if (lane == 31) warp_sums[wid] = x;
        __syncthreads();
        if (wid == 0) {
            int s = warp_sums[lane];
#pragma unroll
            for (int d = 1; d < 32; d <<= 1) {
                int t = __shfl_up_sync(0xffffffffu, s, d);
                if (lane >= d) s += t;
            }
            warp_sums[lane] = s;
        }
        __syncthreads();
        int warp_prefix = (wid > 0) ? warp_sums[wid - 1] : 0;
        int incl = warp_prefix + x;
        if (i < NN) {
            g_off[i]  = carry + incl - v;
            g_dinv[i] = rsqrtf((float)(v + 1));
            g_cur[i]  = 0;
        }
        carry += warp_sums[31];
        __syncthreads();
    }
    if (tid == 0) g_off[NN] = carry;
}
__global__ void fill_kernel(const int* __restrict__ src, const int* __restrict__ tgt) {
    int base = (blockIdx.x * blockDim.x + threadIdx.x) * 4;
    if (base + 3 < NE) {
        int4 t = *(const int4*)(tgt + base);
        int4 s = *(const int4*)(src + base);
        int p0 = g_off[t.x] + atomicAdd(&g_cur[t.x], 1);
        int p1 = g_off[t.y] + atomicAdd(&g_cur[t.y], 1);
        int p2 = g_off[t.z] + atomicAdd(&g_cur[t.z], 1);
        int p3 = g_off[t.w] + atomicAdd(&g_cur[t.w], 1);
        g_el[p0] = s.x; g_el[p1] = s.y; g_el[p2] = s.z; g_el[p3] = s.w;
    }
}

// ---------------------------------------------------------------------------
// Big GEMM via mma.sync bf16 split; W staged from precomputed splits.
// ---------------------------------------------------------------------------
#define MB_AHI 0
#define MB_ALO 6144
#define MB_BHI 12288
#define MB_BLO 16128
#define MB_SMEM 51200

__global__ void __launch_bounds__(256)
gemm_big_mma(const float* __restrict__ X,
             const float* __restrict__ bias,
             const float* __restrict__ gamma,
             const float* __restrict__ beta,
             float* __restrict__ out)
{
    extern __shared__ char smx[];
    const uint32_t sb = smem_u32(smx);
    const int tid = threadIdx.x;
    const int wid = tid >> 5, lane = tid & 31;
    const int r0 = blockIdx.x * 128;
    const int m0 = wid * 16;

    float acc[56];
#pragma unroll
    for (int i = 0; i < 56; i++) acc[i] = 0.f;

    float4 ax0, ax1;
    uint4 w0r, w1r;
    const int ar = tid >> 1, akc = (tid & 1) * 8;
    const int s0buf = tid / 224, s0idx = tid % 224;
    const int s0row = s0idx / 14, s0c = s0idx % 14;
    const int s1idx = tid + 32;
    const int s1row = s1idx / 14, s1c = s1idx % 14;

    auto load_chunk = [&](int t) {
        const int k0 = t * 16;
        int row = r0 + ar;
        const float* xp = X + (size_t)row * D_IN + k0 + akc;
        if (row < NN && k0 + akc + 8 <= D_IN) {
            ax0 = *(const float4*)xp;
            ax1 = *(const float4*)(xp + 4);
        } else {
            float tv[8];
#pragma unroll
            for (int j = 0; j < 8; j++)
                tv[j] = (row < NN && k0 + akc + j < D_IN) ? xp[j] : 0.f;
            ax0 = make_float4(tv[0], tv[1], tv[2], tv[3]);
            ax1 = make_float4(tv[4], tv[5], tv[6], tv[7]);
        }
        {
            const __nv_bfloat16* srcw = s0buf ? g_W1l : g_W1h;
            w0r = *(const uint4*)(srcw + (k0 + s0row) * 112 + s0c * 8);
        }
        if (tid < 192)
            w1r = *(const uint4*)(g_W1l + (k0 + s1row) * 112 + s1c * 8);
    };

    auto sts_chunk = [&]() {
        uint2 h0, l0, h1, l1;
        split4(ax0, h0, l0);
        split4(ax1, h1, l1);
        uint32_t aoff = (uint32_t)(ar * 48 + akc * 2);
        *(uint4*)(smx + MB_AHI + aoff) = make_uint4(h0.x, h0.y, h1.x, h1.y);
        *(uint4*)(smx + MB_ALO + aoff) = make_uint4(l0.x, l0.y, l1.x, l1.y);
        *(uint4*)(smx + (s0buf ? MB_BLO : MB_BHI) + s0row * 240 + s0c * 16) = w0r;
        if (tid < 192)
            *(uint4*)(smx + MB_BLO + s1row * 240 + s1c * 16) = w1r;
    };

    const uint32_t a_addr_off =
        (uint32_t)((m0 + (lane & 15)) * 48 + (lane >> 4) * 16);
    const uint32_t b_addr_row = (uint32_t)((lane & 15) * 240 + (lane >> 4) * 16);

    load_chunk(0);
    for (int t = 0; t < 32; t++) {
        __syncthreads();
        sts_chunk();
        __syncthreads();
        if (t + 1 < 32) load_chunk(t + 1);

        uint32_t ah[4], al[4];
        ldsm4(ah, sb + MB_AHI + a_addr_off);
        ldsm4(al, sb + MB_ALO + a_addr_off);
#pragma unroll
        for (int p = 0; p < 7; p++) {
            uint32_t bh[4], bl[4];
            uint32_t bo = b_addr_row + (uint32_t)(p * 32);
            ldsm4t(bh, sb + MB_BHI + bo);
            ldsm4t(bl, sb + MB_BLO + bo);
#pragma unroll
            for (int h = 0; h < 2; h++) {
                float* c = &acc[p * 8 + h * 4];
                mma16816(c, ah, bh[2 * h], bh[2 * h + 1]);
                mma16816(c, ah, bl[2 * h], bl[2 * h + 1]);
                mma16816(c, al, bh[2 * h], bh[2 * h + 1]);
            }
        }
    }

    __syncthreads();
    float* sC = (float*)smx;
#pragma unroll
    for (int p = 0; p < 7; p++) {
#pragma unroll
        for (int h = 0; h < 2; h++) {
            int n0 = p * 16 + h * 8;
            int col = n0 + (lane & 3) * 2;
            if (col < D_HID) {
                int rA = m0 + (lane >> 2);
                float b0v = bias[col], b1v = bias[col + 1];
                const float* c = &acc[p * 8 + h * 4];
                sC[rA * D_HID + col]           = c[0] + b0v;
                sC[rA * D_HID + col + 1]       = c[1] + b1v;
                sC[(rA + 8) * D_HID + col]     = c[2] + b0v;
                sC[(rA + 8) * D_HID + col + 1] = c[3] + b1v;
            }
        }
    }
    __syncthreads();
    for (int r = wid; r < 128; r += 8) {
        int row = r0 + r;
        float vals[4];
        float s = 0.f, sq = 0.f;
#pragma unroll
        for (int q = 0; q < 4; q++) {
            int c = lane + 32 * q;
            float v = (c < D_HID) ? sC[r * D_HID + c] : 0.f;
            vals[q] = v; s += v; sq += v * v;
        }
#pragma unroll
        for (int o2 = 16; o2 > 0; o2 >>= 1) {
            s  += __shfl_xor_sync(0xffffffffu, s,  o2);
            sq += __shfl_xor_sync(0xffffffffu, sq, o2);
        }
        float mean = s / D_HID;
        float var  = sq / D_HID - mean * mean;
        float rstd = rsqrtf(var + 1e-5f);
        if (row < NN) {
#pragma unroll
            for (int q = 0; q < 4; q++) {
                int c = lane + 32 * q;
                if (c < D_HID)
                    out[row * D_HID + c] =
                        fmaxf((vals[q] - mean) * rstd * gamma[c] + beta[c], 0.f);
            }
        }
    }
}

// ---------------------------------------------------------------------------
// Small GEMM on mma.sync split-bf16; B tiles memcpy'd from precomputed splits.
// 256 threads, 8 warps, warp owns 16-row strip x full N. (R12 winner)
// NOUT = 100 or 64. EPI: 2 = +bias,LN,ReLU | 3 = *dinv | 4 = dual (wA+bias, wB)
// ---------------------------------------------------------------------------
#define SG_AHI 0
#define SG_ALO 30720
#define SG_BHI 61440
#define SG_BLO 88320
#define SG_TOT 115200

template<int NOUT, int EPI>
__global__ void __launch_bounds__(256)
gemm_small_mma(const float* __restrict__ A, int widx, int widx2,
               const float* __restrict__ bias,
               const float* __restrict__ gamma,
               const float* __restrict__ beta,
               float* __restrict__ out,
               float* __restrict__ out2)
{
    constexpr int NP = (NOUT == 64) ? 4 : 7;       // n16-tiles
    extern __shared__ char smx[];
    const uint32_t sb = smem_u32(smx);
    const int tid = threadIdx.x;
    const int wid = tid >> 5, lane = tid & 31;
    const int r0 = blockIdx.x * 128;
    const int m0 = wid * 16;

    // Zero A region (covers k-pad cols 100..119)
    for (int i = tid * 16; i < 61440; i += 256 * 16)
        *(uint4*)(smx + i) = make_uint4(0, 0, 0, 0);
    __syncthreads();

    // Convert A [128 x 100] -> hi/lo bf16, pitch 240B
    for (int i = tid; i < 128 * 25; i += 256) {
        int r = i / 25, q = i % 25;
        int row = r0 + r;
        float4 v = make_float4(0.f, 0.f, 0.f, 0.f);
        if (row < NN) v = *(const float4*)(A + (size_t)row * 100 + q * 4);
        uint2 hi, lo; split4(v, hi, lo);
        *(uint2*)(smx + SG_AHI + r * 240 + q * 8) = hi;
        *(uint2*)(smx + SG_ALO + r * 240 + q * 8) = lo;
    }
    // Copy B tile (precomputed, layout-identical, padding included)
    {
        const uint4* gh = (const uint4*)g_Wh[widx];
        const uint4* gl = (const uint4*)g_Wl[widx];
        for (int i = tid; i < 1680; i += 256) {
            ((uint4*)(smx + SG_BHI))[i] = gh[i];
            ((uint4*)(smx + SG_BLO))[i] = gl[i];
        }
    }
    __syncthreads();

    const uint32_t a_off = (uint32_t)((m0 + (lane & 15)) * 240 + (lane >> 4) * 16);
    const uint32_t b_row = (uint32_t)((lane & 15) * 240 + (lane >> 4) * 16);

    float acc[NP * 8];
    auto run_pass = [&]() {
#pragma unroll
        for (int i = 0; i < NP * 8; i++) acc[i] = 0.f;
#pragma unroll
        for (int kc = 0; kc < 7; kc++) {
            uint32_t ah[4], al[4];
            ldsm4(ah, sb + SG_AHI + a_off + kc * 32);
            ldsm4(al, sb + SG_ALO + a_off + kc * 32);
#pragma unroll
            for (int p = 0; p < NP; p++) {
                uint32_t bh[4], bl[4];
                uint32_t bo = b_row + (uint32_t)(kc * 3840 + p * 32);
                ldsm4t(bh, sb + SG_BHI + bo);
                ldsm4t(bl, sb + SG_BLO + bo);
#pragma unroll
                for (int h = 0; h < 2; h++) {
                    float* c = &acc[p * 8 + h * 4];
                    mma16816(c, ah, bh[2 * h], bh[2 * h + 1]);
                    mma16816(c, ah, bl[2 * h], bl[2 * h + 1]);
                    mma16816(c, al, bh[2 * h], bh[2 * h + 1]);
                }
            }
        }
    };

    run_pass();

    const int rA = m0 + (lane >> 2);
    const int rowA = r0 + rA, rowB = rowA + 8;

    if (EPI == 2) {
        __syncthreads();
        float* sC = (float*)smx;
#pragma unroll
        for (int p = 0; p < NP; p++) {
#pragma unroll
            for (int h = 0; h < 2; h++) {
                int col = p * 16 + h * 8 + (lane & 3) * 2;
                if (col < NOUT) {
                    float b0v = bias[col], b1v = bias[col + 1];
                    const float* c = &acc[p * 8 + h * 4];
                    sC[rA * NOUT + col]           = c[0] + b0v;
                    sC[rA * NOUT + col + 1]       = c[1] + b1v;
                    sC[(rA + 8) * NOUT + col]     = c[2] + b0v;
                    sC[(rA + 8) * NOUT + col + 1] = c[3] + b1v;
                }
            }
        }
        __syncthreads();
        for (int r = wid; r < 128; r += 8) {
            int row = r0 + r;
            float vals[4];
            float s = 0.f, sq = 0.f;
#pragma unroll
            for (int q = 0; q < 4; q++) {
                int c = lane + 32 * q;
                float v = (c < NOUT) ? sC[r * NOUT + c] : 0.f;
                vals[q] = v; s += v; sq += v * v;
            }
#pragma unroll
            for (int o2 = 16; o2 > 0; o2 >>= 1) {
                s  += __shfl_xor_sync(0xffffffffu, s,  o2);
                sq += __shfl_xor_sync(0xffffffffu, sq, o2);
            }
            float mean = s / NOUT;
            float var  = sq / NOUT - mean * mean;
            float rstd = rsqrtf(var + 1e-5f);
            if (row < NN) {
#pragma unroll
                for (int q = 0; q < 4; q++) {
                    int c = lane + 32 * q;
                    if (c < NOUT)
                        out[row * NOUT + c] =
                            fmaxf((vals[q] - mean) * rstd * gamma[c] + beta[c], 0.f);
                }
            }
        }
    } else if (EPI == 3) {
        float d0 = (rowA < NN) ? g_dinv[rowA] : 0.f;
        float d1 = (rowB < NN) ? g_dinv[rowB] : 0.f;
#pragma unroll
        for (int p = 0; p < NP; p++) {
#pragma unroll
            for (int h = 0; h < 2; h++) {
                int col = p * 16 + h * 8 + (lane & 3) * 2;
                if (col < NOUT) {
                    const float* c = &acc[p * 8 + h * 4];
                    if (rowA < NN) {
                        out[(size_t)rowA * NOUT + col]     = d0 * c[0];
                        out[(size_t)rowA * NOUT + col + 1] = d0 * c[1];
                    }
                    if (rowB < NN) {
                        out[(size_t)rowB * NOUT + col]     = d1 * c[2];
                        out[(size_t)rowB * NOUT + col + 1] = d1 * c[3];
                    }
                }
            }
        }
    } else {  // EPI == 4: dual, two passes over same B buffer
#pragma unroll
        for (int p = 0; p < NP; p++) {
#pragma unroll
            for (int h = 0; h < 2; h++) {
                int col = p * 16 + h * 8 + (lane & 3) * 2;
                if (col < NOUT) {
                    const float* c = &acc[p * 8 + h * 4];
                    float b0v = bias[col], b1v = bias[col + 1];
                    if (rowA < NN) {
                        out[(size_t)rowA * NOUT + col]     = c[0] + b0v;
                        out[(size_t)rowA * NOUT + col + 1] = c[1] + b1v;
                    }
                    if (rowB < NN) {
                        out[(size_t)rowB * NOUT + col]     = c[2] + b0v;
                        out[(size_t)rowB * NOUT + col + 1] = c[3] + b1v;
                    }
                }
            }
        }
        __syncthreads();
        {
            const uint4* gh = (const uint4*)g_Wh[widx2];
            const uint4* gl = (const uint4*)g_Wl[widx2];
            for (int i = tid; i < 1680; i += 256) {
                ((uint4*)(smx + SG_BHI))[i] = gh[i];
                ((uint4*)(smx + SG_BLO))[i] = gl[i];
            }
        }
        __syncthreads();
        run_pass();
#pragma unroll
        for (int p = 0; p < NP; p++) {
#pragma unroll
            for (int h = 0; h < 2; h++) {
                int col = p * 16 + h * 8 + (lane & 3) * 2;
                if (col < NOUT) {
                    const float* c = &acc[p * 8 + h * 4];
                    if (rowA < NN) {
                        out2[(size_t)rowA * NOUT + col]     = c[0];
                        out2[(size_t)rowA * NOUT + col + 1] = c[1];
                    }
                    if (rowB < NN) {
                        out2[(size_t)rowB * NOUT + col]     = c[2];
                        out2[(size_t)rowB * NOUT + col + 1] = c[3];
                    }
                }
            }
        }
    }
}

// ---------------------------------------------------------------------------
// Gather aggregation (warp per node), 4-way edge ILP. (unchanged)
// ---------------------------------------------------------------------------
template<int M4, int MODE>
__global__ void gather_kernel(const float* __restrict__ h,
                              const float* __restrict__ self,
                              const float* __restrict__ bias,
                              float* __restrict__ out)
{
    int w = (blockIdx.x * blockDim.x + threadIdx.x) >> 5;
    if (w >= NN) return;
    const int lane = threadIdx.x & 31;
    const bool act = lane < M4;
    const float4* h4 = (const float4*)h;

    float4 a0 = make_float4(0.f, 0.f, 0.f, 0.f);
    float4 a1 = a0, a2 = a0, a3 = a0;
    if (act) {
        if (MODE == 0) a0 = ((const float4*)self)[w * M4 + lane];
        else           a0 = h4[w * M4 + lane];
    }

    const int off = g_off[w];
    const int dg  = g_off[w + 1] - off;
    for (int base = 0; base < dg; base += 32) {
        int idx = base + lane;
        int myel = (idx < dg) ? g_el[off + idx] : 0;
        int cnt = dg - base; if (cnt > 32) cnt = 32;
        int j = 0;
        for (; j + 3 < cnt; j += 4) {
            int s0 = __shfl_sync(0xffffffffu, myel, j);
            int s1 = __shfl_sync(0xffffffffu, myel, j + 1);
            int s2 = __shfl_sync(0xffffffffu, myel, j + 2);
            int s3 = __shfl_sync(0xffffffffu, myel, j + 3);
            if (act) {
                float4 v0 = h4[s0 * M4 + lane];
                float4 v1 = h4[s1 * M4 + lane];
                float4 v2 = h4[s2 * M4 + lane];
                float4 v3 = h4[s3 * M4 + lane];
                a0.x += v0.x; a0.y += v0.y; a0.z += v0.z; a0.w += v0.w;
                a1.x += v1.x; a1.y += v1.y; a1.z += v1.z; a1.w += v1.w;
                a2.x += v2.x; a2.y += v2.y; a2.z += v2.z; a2.w += v2.w;
                a3.x += v3.x; a3.y += v3.y; a3.z += v3.z; a3.w += v3.w;
            }
        }
        for (; j < cnt; j++) {
            int s0 = __shfl_sync(0xffffffffu, myel, j);
            if (act) {
                float4 v0 = h4[s0 * M4 + lane];
                a0.x += v0.x; a0.y += v0.y; a0.z += v0.z; a0.w += v0.w;
            }
        }
    }
    float4 acc;
    acc.x = (a0.x + a1.x) + (a2.x + a3.x);
    acc.y = (a0.y + a1.y) + (a2.y + a3.y);
    acc.z = (a0.z + a1.z) + (a2.z + a3.z);
    acc.w = (a0.w + a1.w) + (a2.w + a3.w);

    if (MODE == 0) {
        if (act) {
            float4 o;
            o.x = fmaxf(acc.x, 0.f); o.y = fmaxf(acc.y, 0.f);
            o.z = fmaxf(acc.z, 0.f); o.w = fmaxf(acc.w, 0.f);
            ((float4*)out)[w * M4 + lane] = o;
        }
    } else if (MODE == 1) {
        if (act) {
            float di = g_dinv[w];
            float4 b = ((const float4*)bias)[lane];
            float4 o;
            o.x = fmaxf(fmaf(di, acc.x, b.x), 0.f);
            o.y = fmaxf(fmaf(di, acc.y, b.y), 0.f);
            o.z = fmaxf(fmaf(di, acc.z, b.z), 0.f);
            o.w = fmaxf(fmaf(di, acc.w, b.w), 0.f);
            ((float4*)out)[w * M4 + lane] = o;
        }
    } else {
        float di = g_dinv[w];
        float4 v = make_float4(0.f, 0.f, 0.f, 0.f);
        if (act) {
            float4 b = ((const float4*)bias)[lane];
            v.x = fmaf(di, acc.x, b.x); v.y = fmaf(di, acc.y, b.y);
            v.z = fmaf(di, acc.z, b.z); v.w = fmaf(di, acc.w, b.w);
        }
        float m = act ? fmaxf(fmaxf(v.x, v.y), fmaxf(v.z, v.w)) : -3.4e38f;
#pragma unroll
        for (int o2 = 16; o2 > 0; o2 >>= 1)
            m = fmaxf(m, __shfl_xor_sync(0xffffffffu, m, o2));
        float se = act ? (expf(v.x - m) + expf(v.y - m) + expf(v.z - m) + expf(v.w - m)) : 0.f;
#pragma unroll
        for (int o2 = 16; o2 > 0; o2 >>= 1)
            se += __shfl_xor_sync(0xffffffffu, se, o2);
        float lse = m + logf(se);
        if (act) {
            float4 o;
            o.x = v.x - lse; o.y = v.y - lse; o.z = v.z - lse; o.w = v.w - lse;
            ((float4*)out)[w * M4 + lane] = o;
        }
    }
}

extern "C" void kernel_launch(void* const* d_in, const int* in_sizes, int n_in,
                              void* d_out, int out_size)
{
    const float* X     = (const float*)d_in[0];
    const int*   ei    = (const int*)  d_in[1];
    const float* W1    = (const float*)d_in[3];
    const float* b1    = (const float*)d_in[4];
    const float* g1    = (const float*)d_in[5];
    const float* be1   = (const float*)d_in[6];
    const float* W2    = (const float*)d_in[7];
    const float* b2    = (const float*)d_in[8];
    const float* g2    = (const float*)d_in[9];
    const float* be2   = (const float*)d_in[10];
    const float* Wrel  = (const float*)d_in[11];
    const float* Wself = (const float*)d_in[12];
    const float* rb    = (const float*)d_in[13];
    const float* c1W   = (const float*)d_in[14];
    const float* c1b   = (const float*)d_in[15];
    const float* c2W   = (const float*)d_in[16];
    const float* c2b   = (const float*)d_in[17];
    float* out = (float*)d_out;

    const int* src = ei;
    const int* tgt = ei + NE;

    float *B1, *B2, *B3, *B4;
    cudaGetSymbolAddress((void**)&B1, g_B1);
    cudaGetSymbolAddress((void**)&B2, g_B2);
    cudaGetSymbolAddress((void**)&B3, g_B3);
    cudaGetSymbolAddress((void**)&B4, g_B4);

    cudaFuncSetAttribute(gemm_big_mma,
                         cudaFuncAttributeMaxDynamicSharedMemorySize, MB_SMEM);
    cudaFuncSetAttribute(gemm_small_mma<100, 2>,
                         cudaFuncAttributeMaxDynamicSharedMemorySize, SG_TOT);
    cudaFuncSetAttribute(gemm_small_mma<100, 3>,
                         cudaFuncAttributeMaxDynamicSharedMemorySize, SG_TOT);
    cudaFuncSetAttribute(gemm_small_mma<100, 4>,
                         cudaFuncAttributeMaxDynamicSharedMemorySize, SG_TOT);
    cudaFuncSetAttribute(gemm_small_mma<64, 3>,
                         cudaFuncAttributeMaxDynamicSharedMemorySize, SG_TOT);

    const int GB = (NN + 127) / 128;   // 391
    const int GGATHER = (NN * 32 + 255) / 256;

    // Fork a side stream for the CSR build (overlaps the transform GEMMs).
    cudaStream_t s2;
    cudaEvent_t evFork, evJoin;
    cudaStreamCreateWithFlags(&s2, cudaStreamNonBlocking);
    cudaEventCreateWithFlags(&evFork, cudaEventDisableTiming);
    cudaEventCreateWithFlags(&evJoin, cudaEventDisableTiming);

    cudaEventRecord(evFork, 0);
    cudaStreamWaitEvent(s2, evFork, 0);

    deg_zero_kernel <<<(NN / 4 + 255) / 256, 256, 0, s2>>>();
    deg_count_kernel<<<(NE / 4 + 255) / 256, 256, 0, s2>>>(tgt);
    scan_kernel     <<<1, 1024, 0, s2>>>();
    fill_kernel     <<<(NE / 4 + 255) / 256, 256, 0, s2>>>(src, tgt);
    cudaEventRecord(evJoin, s2);

    // Weight splits (once, tiny)
    wsplit_kernel<<<(512 * 112 + 5 * 13440 + 255) / 256, 256>>>(
        W1, W2, Wself, Wrel, c1W, c2W);

    // transform: (Linear -> LN -> ReLU) x2, both on mma.sync tensor path
    gemm_big_mma<<<GB, 256, MB_SMEM>>>(X, b1, g1, be1, B1);
    gemm_small_mma<100, 2><<<GB, 256, SG_TOT>>>(
        B1, 0, 0, b2, g2, be2, B2, nullptr);

    // RGCN: dual GEMM (Wself + rb -> B3, Wrel -> B4), then gather
    gemm_small_mma<100, 4><<<GB, 256, SG_TOT>>>(
        B2, 1, 2, rb, nullptr, nullptr, B3, B4);

    cudaStreamWaitEvent(0, evJoin, 0);
    gather_kernel<25, 0><<<GGATHER, 256>>>(B4, B3, nullptr, B1);

    // GCNConv1
    gemm_small_mma<100, 3><<<GB, 256, SG_TOT>>>(
        B1, 3, 0, nullptr, nullptr, nullptr, B2, nullptr);
    gather_kernel<25, 1><<<GGATHER, 256>>>(B2, nullptr, c1b, B3);

    // GCNConv2 (->64) + log_softmax
    gemm_small_mma<64, 3><<<GB, 256, SG_TOT>>>(
        B3, 4, 0, nullptr, nullptr, nullptr, B4, nullptr);
    gather_kernel<16, 2><<<GGATHER, 256>>>(B4, nullptr, c2b, out);

    cudaEventDestroy(evFork);
    cudaEventDestroy(evJoin);
    cudaStreamDestroy(s2);
}